// round 13
// baseline (speedup 1.0000x reference)
#include <cuda_runtime.h>
#include <cuda_bf16.h>
#include <cuda_fp16.h>
#include <cstdint>

#define D_MODEL  1024
#define N_HEADS  16
#define HEAD_DIM 64
#define BATCH    2
#define SEQ      2048
#define M_TOTAL  (BATCH * SEQ)   // 4096
#define QSCALE   0.18033688011112042f   // 0.125 * log2(e)

// ---------------------------------------------------------------------------
// Device-global scratch (allocation-free rule) — all fp16, hi-only QKV/O
// ---------------------------------------------------------------------------
#define PHSZ (BATCH * N_HEADS * SEQ * HEAD_DIM)   // 4M elems
__device__ __align__(16) __half g_Qh[PHSZ];
__device__ __align__(16) __half g_Kh[PHSZ];
__device__ __align__(16) __half g_Vh[PHSZ];
__device__ __align__(16) __half g_xh[M_TOTAL * D_MODEL];
__device__ __align__(16) __half g_xl[M_TOTAL * D_MODEL];
__device__ __align__(16) __half g_Wth[4 * D_MODEL * D_MODEL]; // W^T hi [N,K]
__device__ __align__(16) __half g_Oh[M_TOTAL * D_MODEL];

// ---------------------------------------------------------------------------
// helpers (compute_103-legal: ldmatrix / mma.sync / cp.async / ex2.approx)
// ---------------------------------------------------------------------------
__device__ __forceinline__ uint32_t smem_u32(const void* p) {
    uint32_t a;
    asm("{ .reg .u64 t; cvta.to.shared.u64 t, %1; cvt.u32.u64 %0, t; }"
        : "=r"(a) : "l"(p));
    return a;
}
__device__ __forceinline__ void ldsm4(uint32_t* r, uint32_t addr) {
    asm volatile("ldmatrix.sync.aligned.m8n8.x4.shared.b16 {%0,%1,%2,%3}, [%4];"
        : "=r"(r[0]), "=r"(r[1]), "=r"(r[2]), "=r"(r[3]) : "r"(addr));
}
__device__ __forceinline__ void ldsm4t(uint32_t* r, uint32_t addr) {
    asm volatile("ldmatrix.sync.aligned.m8n8.x4.trans.shared.b16 {%0,%1,%2,%3}, [%4];"
        : "=r"(r[0]), "=r"(r[1]), "=r"(r[2]), "=r"(r[3]) : "r"(addr));
}
__device__ __forceinline__ void mma_f16(float* c, const uint32_t* a,
                                        uint32_t b0, uint32_t b1) {
    asm volatile(
        "mma.sync.aligned.m16n8k16.row.col.f32.f16.f16.f32 "
        "{%0,%1,%2,%3}, {%4,%5,%6,%7}, {%8,%9}, {%0,%1,%2,%3};"
        : "+f"(c[0]), "+f"(c[1]), "+f"(c[2]), "+f"(c[3])
        : "r"(a[0]), "r"(a[1]), "r"(a[2]), "r"(a[3]), "r"(b0), "r"(b1));
}
__device__ __forceinline__ float exp2a(float x) {
    float r; asm("ex2.approx.f32 %0, %1;" : "=f"(r) : "f"(x)); return r;
}
__device__ __forceinline__ uint32_t f16x2pk(float lo, float hi) {
    uint32_t r;
    asm("cvt.rn.f16x2.f32 %0, %1, %2;" : "=r"(r) : "f"(hi), "f"(lo));
    return r;
}
__device__ __forceinline__ float h_lo(uint32_t r) {
    __half2 h = *(const __half2*)&r;
    return __half2float(h.x);
}
__device__ __forceinline__ float h_hi(uint32_t r) {
    __half2 h = *(const __half2*)&r;
    return __half2float(h.y);
}

#define CP16(saddr, gptr) \
    asm volatile("cp.async.cg.shared.global [%0], [%1], 16;" \
        :: "r"(saddr), "l"(gptr) : "memory")
#define CP_COMMIT() asm volatile("cp.async.commit_group;" ::: "memory")
#define CP_WAIT0()  asm volatile("cp.async.wait_group 0;" ::: "memory")
#define CP_WAIT1()  asm volatile("cp.async.wait_group 1;" ::: "memory")

// ---------------------------------------------------------------------------
// Fused prep: z=0 -> x fp32 -> fp16 hi/lo split; z=1..4 -> W transpose (hi).
// ---------------------------------------------------------------------------
__global__ __launch_bounds__(256) void prep(
    const float* __restrict__ x,
    const float* __restrict__ Wq, const float* __restrict__ Wk,
    const float* __restrict__ Wv, const float* __restrict__ Wo,
    __half* __restrict__ xh, __half* __restrict__ xl,
    __half* __restrict__ Wth)
{
    __shared__ float t[32][33];
    const int z = blockIdx.z;
    const int tid = threadIdx.x;

    if (z == 0) {
        const int bid = blockIdx.y * 32 + blockIdx.x;     // 0..1023
        #pragma unroll
        for (int it = 0; it < 4; ++it) {
            const int i = it * (1024 * 256) + bid * 256 + tid;
            float4 v = ((const float4*)x)[i];
            uint32_t h0 = f16x2pk(v.x, v.y), h1 = f16x2pk(v.z, v.w);
            uint32_t l0 = f16x2pk(v.x - h_lo(h0), v.y - h_hi(h0));
            uint32_t l1 = f16x2pk(v.z - h_lo(h1), v.w - h_hi(h1));
            ((uint2*)xh)[i] = make_uint2(h0, h1);
            ((uint2*)xl)[i] = make_uint2(l0, l1);
        }
        return;
    }

    const float* W = (z == 1) ? Wq : (z == 2) ? Wk : (z == 3) ? Wv : Wo;
    const size_t WSZ = (size_t)D_MODEL * D_MODEL;
    __half* Th = Wth + (size_t)(z - 1) * WSZ;

    const int bx = blockIdx.x * 32;   // n block
    const int by = blockIdx.y * 32;   // k block
    const int xx = tid & 31, yy = tid >> 5;   // 32 x 8
    #pragma unroll
    for (int j = 0; j < 32; j += 8)
        t[yy + j][xx] = W[(by + yy + j) * D_MODEL + bx + xx];
    __syncthreads();
    #pragma unroll
    for (int j = 0; j < 32; j += 8) {
        float v = t[xx][yy + j];               // (k=by+xx, n=bx+yy+j)
        Th[(bx + yy + j) * D_MODEL + by + xx] = __float2half_rn(v);
    }
}

// ---------------------------------------------------------------------------
// GEMM mainloop: fp16 via mma.sync, 128x128 tile, K-chunk 32,
// 3-stage cp.async pipeline with ONE barrier per chunk, 2 CTAs/SM.
// TERMS=2: C = Ah*Bh + Al*Bh   TERMS=1: C = Ah*Bh
// ---------------------------------------------------------------------------
#define GK     32
#define NKCH   (D_MODEL / GK)        // 32
#define ROW_B  80
#define TILE_B (128 * ROW_B)         // 10240
#define STG3_B (3 * TILE_B)          // 30720 per stage (Ah, Al, Bh)
#define GEMM_SMEM (3 * STG3_B)       // 92160  (x2 CTAs = 184KB < 228KB)

template <int TERMS>
__device__ __forceinline__ void gemm_issue(
    const __half* pAh, const __half* pAl, const __half* pBh,
    uint32_t sb, int slot, int chunk,
    uint32_t w0, uint32_t w1)
{
    const uint32_t s = sb + (uint32_t)slot * STG3_B;
    const int e = chunk * GK;
    CP16(s + w0,              pAh + e);
    CP16(s + w1,              pAh + e + 8);
    if (TERMS >= 2) {
        CP16(s + TILE_B + w0, pAl + e);
        CP16(s + TILE_B + w1, pAl + e + 8);
    }
    CP16(s + 2 * TILE_B + w0, pBh + e);
    CP16(s + 2 * TILE_B + w1, pBh + e + 8);
    CP_COMMIT();
}

template <int TERMS>
__device__ __forceinline__ void gemm_core(
    const __half* __restrict__ Ah, const __half* __restrict__ Al,
    const __half* __restrict__ Bh,
    uint32_t sb, int m0, int n0, float acc[4][4][4])
{
    const int tid  = threadIdx.x;
    const int lane = tid & 31;
    const int wid  = tid >> 5;
    const int wm = (wid & 1) * 64;
    const int wn = (wid >> 1) * 32;

    const int lrow = tid >> 1;
    const int lhalf = tid & 1;
    const __half* pAh = Ah + (size_t)(m0 + lrow) * D_MODEL + lhalf * 16;
    const __half* pAl = (TERMS >= 2)
        ? Al + (size_t)(m0 + lrow) * D_MODEL + lhalf * 16 : nullptr;
    const __half* pBh = Bh + (size_t)(n0 + lrow) * D_MODEL + lhalf * 16;
    const uint32_t w0 = (uint32_t)lrow * ROW_B + (uint32_t)lhalf * 32u;
    const uint32_t w1 = w0 + 16u;

    const uint32_t a_off = (uint32_t)(wm + (lane & 15)) * ROW_B
                         + (uint32_t)(lane >> 4) * 16u;
    const uint32_t b_off = (uint32_t)(wn + ((lane >> 4) << 3) + (lane & 7)) * ROW_B
                         + (uint32_t)((lane >> 3) & 1) * 16u;

    #pragma unroll
    for (int i = 0; i < 4; ++i)
        #pragma unroll
        for (int j = 0; j < 4; ++j)
            #pragma unroll
            for (int r = 0; r < 4; ++r) acc[i][j][r] = 0.f;

    // prologue: stages 0 and 1 in flight
    gemm_issue<TERMS>(pAh, pAl, pBh, sb, 0, 0, w0, w1);
    gemm_issue<TERMS>(pAh, pAl, pBh, sb, 1, 1, w0, w1);

    int slot = 0;        // stage slot of chunk i
    int nslot = 2;       // slot for chunk i+2
    for (int i = 0; i < NKCH; ++i) {
        if (i + 2 < NKCH) CP_WAIT1();   // chunk i landed; i+1 in flight
        else              CP_WAIT0();
        __syncthreads();                // ONE barrier: chunk i visible AND
                                        // all warps past chunk i-1's reads
        if (i + 2 < NKCH)
            gemm_issue<TERMS>(pAh, pAl, pBh, sb, nslot, i + 2, w0, w1);

        const uint32_t stg = sb + (uint32_t)slot * STG3_B;
        #pragma unroll
        for (int ks = 0; ks < 2; ++ks) {
            uint32_t bh[2][4];
            #pragma unroll
            for (int ng = 0; ng < 2; ++ng)
                ldsm4(bh[ng], stg + 2 * TILE_B + b_off + ng * (16 * ROW_B) + ks * 32);
            #pragma unroll
            for (int mt = 0; mt < 4; ++mt) {
                uint32_t ah[4], al[4];
                ldsm4(ah, stg + a_off + mt * (16 * ROW_B) + ks * 32);
                if (TERMS >= 2)
                    ldsm4(al, stg + TILE_B + a_off + mt * (16 * ROW_B) + ks * 32);
                #pragma unroll
                for (int n8 = 0; n8 < 4; ++n8) {
                    const int ng = n8 >> 1, hf = (n8 & 1) * 2;
                    mma_f16(acc[mt][n8], ah, bh[ng][hf], bh[ng][hf + 1]);
                }
                if (TERMS >= 2) {
                    #pragma unroll
                    for (int n8 = 0; n8 < 4; ++n8) {
                        const int ng = n8 >> 1, hf = (n8 & 1) * 2;
                        mma_f16(acc[mt][n8], al, bh[ng][hf], bh[ng][hf + 1]);
                    }
                }
            }
        }

        slot  = (slot  == 2) ? 0 : slot + 1;
        nslot = (nslot == 2) ? 0 : nslot + 1;
    }
}

// QKV projections fused: grid (8, 32, 3); z: 0=Q, 1=K, 2=V. All 2-term, hi out.
__global__ __launch_bounds__(256, 2)
void gemm_qkv(const __half* __restrict__ xh,
              const __half* __restrict__ xl,
              const __half* __restrict__ Wth,
              const float* __restrict__ bq, const float* __restrict__ bk,
              const float* __restrict__ bv,
              __half* __restrict__ Qh, __half* __restrict__ Kh,
              __half* __restrict__ Vh)
{
    extern __shared__ char smem[];
    const uint32_t sb = smem_u32(smem);
    const int z = blockIdx.z;
    const size_t WSZ = (size_t)D_MODEL * D_MODEL;
    const __half* Bh = Wth + (size_t)z * WSZ;
    const float* bias = (z == 0) ? bq : (z == 1) ? bk : bv;
    const float scale = (z == 0) ? QSCALE : 1.0f;
    __half* Ch = (z == 0) ? Qh : (z == 1) ? Kh : Vh;

    const int m0 = blockIdx.y * 128;
    const int n0 = blockIdx.x * 128;

    float acc[4][4][4];
    gemm_core<2>(xh, xl, Bh, sb, m0, n0, acc);

    const int lane = threadIdx.x & 31;
    const int wid  = threadIdx.x >> 5;
    const int wm = (wid & 1) * 64, wn = (wid >> 1) * 32;
    const int mrow = lane >> 2, ncol = (lane & 3) * 2;
    #pragma unroll
    for (int mt = 0; mt < 4; ++mt) {
        #pragma unroll
        for (int n8 = 0; n8 < 4; ++n8) {
            const int n = n0 + wn + n8 * 8 + ncol;
            const float bx = bias[n], by = bias[n + 1];
            #pragma unroll
            for (int h2 = 0; h2 < 2; ++h2) {
                const int m = m0 + wm + mt * 16 + mrow + h2 * 8;
                const float vx = (acc[mt][n8][h2 * 2 + 0] + bx) * scale;
                const float vy = (acc[mt][n8][h2 * 2 + 1] + by) * scale;
                const int b = m >> 11, s = m & (SEQ - 1);
                const int hh = n >> 6, hd = n & 63;
                const size_t idx =
                    ((size_t)(b * N_HEADS + hh) * SEQ + s) * HEAD_DIM + hd;
                *(uint32_t*)&Ch[idx] = f16x2pk(vx, vy);
            }
        }
    }
}

// Output projection: 1-term fp16, fp32 out row-major.
__global__ __launch_bounds__(256, 2)
void gemm_out(const __half* __restrict__ Ah,
              const __half* __restrict__ Bh,
              const float* __restrict__ bias, float* __restrict__ C)
{
    extern __shared__ char smem[];
    const uint32_t sb = smem_u32(smem);
    const int m0 = blockIdx.y * 128;
    const int n0 = blockIdx.x * 128;

    float acc[4][4][4];
    gemm_core<1>(Ah, nullptr, Bh, sb, m0, n0, acc);

    const int lane = threadIdx.x & 31;
    const int wid  = threadIdx.x >> 5;
    const int wm = (wid & 1) * 64, wn = (wid >> 1) * 32;
    const int mrow = lane >> 2, ncol = (lane & 3) * 2;
    #pragma unroll
    for (int mt = 0; mt < 4; ++mt) {
        #pragma unroll
        for (int n8 = 0; n8 < 4; ++n8) {
            const int n = n0 + wn + n8 * 8 + ncol;
            const float bx = bias[n], by = bias[n + 1];
            #pragma unroll
            for (int h2 = 0; h2 < 2; ++h2) {
                const int m = m0 + wm + mt * 16 + mrow + h2 * 8;
                float2 v;
                v.x = acc[mt][n8][h2 * 2 + 0] + bx;
                v.y = acc[mt][n8][h2 * 2 + 1] + by;
                *(float2*)&C[(size_t)m * D_MODEL + n] = v;
            }
        }
    }
}

// ---------------------------------------------------------------------------
// Tensor-core causal flash attention, fp16 operands (R12 known-good).
// S = Qh·Kh.  O += Ph·Vh.  Output hi only.
// cp.async double-buffered K/V pipeline; skip-rescale.
// ---------------------------------------------------------------------------
#define SROWB 144
#define ATILE (64 * SROWB)               // 9216
#define ATT_SMEM (5 * ATILE)             // 46080

__device__ __forceinline__ void cp_tile2(uint32_t sbase, const __half* gK,
                                         const __half* gV, int tid)
{
    #pragma unroll
    for (int i = 0; i < 4; ++i) {
        const int c = tid + 128 * i;
        const uint32_t sa = (uint32_t)(c >> 3) * SROWB + (uint32_t)(c & 7) * 16u;
        CP16(sbase + sa, gK + 8 * c);
        CP16(sbase + ATILE + sa, gV + 8 * c);
    }
}

__global__ __launch_bounds__(128)
void flash_mma(const __half* __restrict__ Qh_,
               const __half* __restrict__ Kh_, const __half* __restrict__ Vh_,
               __half* __restrict__ Oh)
{
    extern __shared__ char smem[];
    const uint32_t sb = smem_u32(smem);

    const int tid = threadIdx.x, lane = tid & 31, w = tid >> 5;
    const int bh = blockIdx.y;
    const int qb = gridDim.x - 1 - blockIdx.x;   // long blocks first
    const int q0 = qb * 64;
    const size_t base = (size_t)bh * SEQ * HEAD_DIM;

    // prologue: Q + K/V stage 0, one cp.async group
    {
        const __half* gQh = Qh_ + base + (size_t)q0 * 64;
        #pragma unroll
        for (int i = 0; i < 4; ++i) {
            const int c = tid + 128 * i;
            const uint32_t sa = (uint32_t)(c >> 3) * SROWB + (uint32_t)(c & 7) * 16u;
            CP16(sb + sa, gQh + 8 * c);
        }
        cp_tile2(sb + ATILE, Kh_ + base, Vh_ + base, tid);
        CP_COMMIT();
    }

    const uint32_t k_nr = (uint32_t)((lane & 7) + ((lane >> 4) << 3));
    const uint32_t k_nc = (uint32_t)(((lane >> 3) & 1) << 3);
    const uint32_t v_nr = (uint32_t)((lane & 7) + (((lane >> 3) & 1) << 3));
    const uint32_t v_nc = (uint32_t)((lane >> 4) << 3);

    uint32_t qh[4][4];
    float o[8][4];
    #pragma unroll
    for (int i = 0; i < 8; ++i)
        #pragma unroll
        for (int j = 0; j < 4; ++j) o[i][j] = 0.f;
    float m0 = -1e30f, m1 = -1e30f, l0 = 0.f, l1 = 0.f;

    const int nt = q0 >> 6;
    for (int it = 0; it <= nt; ++it) {
        __syncthreads();              // all warps done reading stage it^1
        if (it < nt) {
            const size_t g = base + (size_t)(it + 1) * 64 * 64;
            cp_tile2(sb + ATILE + (uint32_t)((it + 1) & 1) * 2 * ATILE,
                     Kh_ + g, Vh_ + g, tid);
            CP_COMMIT();
            CP_WAIT1();
        } else {
            CP_WAIT0();
        }
        __syncthreads();

        if (it == 0) {                // Q fragments (once)
            const int r = (w << 4) + (lane & 15);
            const int c = (lane >> 4) << 3;
            #pragma unroll
            for (int kc = 0; kc < 4; ++kc)
                ldsm4(qh[kc], sb + (uint32_t)r * SROWB
                              + (uint32_t)(kc * 16 + c) * 2);
        }

        const uint32_t sK = sb + ATILE + (uint32_t)(it & 1) * 2 * ATILE;
        const uint32_t sV = sK + ATILE;

        // ---- S = Qh Kh^T ----
        float s[8][4];
        #pragma unroll
        for (int i = 0; i < 8; ++i)
            #pragma unroll
            for (int j = 0; j < 4; ++j) s[i][j] = 0.f;

        #pragma unroll
        for (int nbp = 0; nbp < 4; ++nbp) {
            #pragma unroll
            for (int kc = 0; kc < 4; ++kc) {
                uint32_t kh[4];
                const uint32_t a = sK + (uint32_t)(nbp * 16 + k_nr) * SROWB
                                 + (uint32_t)(kc * 16 + k_nc) * 2;
                ldsm4(kh, a);
                mma_f16(s[2*nbp],   qh[kc], kh[0], kh[1]);
                mma_f16(s[2*nbp+1], qh[kc], kh[2], kh[3]);
            }
        }

        // ---- causal mask (diagonal tile only) ----
        if (it == nt) {
            const int rb = (w << 4) + (lane >> 2);
            #pragma unroll
            for (int nb = 0; nb < 8; ++nb) {
                const int c = nb * 8 + ((lane & 3) << 1);
                if (c     > rb)     s[nb][0] = -1e30f;
                if (c + 1 > rb)     s[nb][1] = -1e30f;
                if (c     > rb + 8) s[nb][2] = -1e30f;
                if (c + 1 > rb + 8) s[nb][3] = -1e30f;
            }
        }

        // ---- online softmax (log2 domain), skip rescale if max unchanged ----
        float mt0 = -1e30f, mt1 = -1e30f;
        #pragma unroll
        for (int nb = 0; nb < 8; ++nb) {
            mt0 = fmaxf(mt0, fmaxf(s[nb][0], s[nb][1]));
            mt1 = fmaxf(mt1, fmaxf(s[nb][2], s[nb][3]));
        }
        mt0 = fmaxf(mt0, __shfl_xor_sync(0xffffffffu, mt0, 1));
        mt0 = fmaxf(mt0, __shfl_xor_sync(0xffffffffu, mt0, 2));
        mt1 = fmaxf(mt1, __shfl_xor_sync(0xffffffffu, mt1, 1));
        mt1 = fmaxf(mt1, __shfl_xor_sync(0xffffffffu, mt1, 2));
        if (mt0 > m0 || mt1 > m1) {
            const float mn0 = fmaxf(m0, mt0), mn1 = fmaxf(m1, mt1);
            const float c0 = exp2a(m0 - mn0), c1 = exp2a(m1 - mn1);
            m0 = mn0; m1 = mn1;
            l0 *= c0;  l1 *= c1;
            #pragma unroll
            for (int nb = 0; nb < 8; ++nb) {
                o[nb][0] *= c0; o[nb][1] *= c0; o[nb][2] *= c1; o[nb][3] *= c1;
            }
        }

        uint32_t ph[4][4];
        #pragma unroll
        for (int nb = 0; nb < 8; ++nb) {
            const float p0 = exp2a(s[nb][0] - m0);
            const float p1 = exp2a(s[nb][1] - m0);
            const float p2 = exp2a(s[nb][2] - m1);
            const float p3 = exp2a(s[nb][3] - m1);
            l0 += p0 + p1;  l1 += p2 + p3;
            const int j = nb >> 1, q = (nb & 1) << 1;
            ph[j][q]     = f16x2pk(p0, p1);
            ph[j][q + 1] = f16x2pk(p2, p3);
        }

        // ---- O += Ph Vh ----
        #pragma unroll
        for (int j = 0; j < 4; ++j) {
            #pragma unroll
            for (int nbp = 0; nbp < 4; ++nbp) {
                uint32_t vh[4];
                const uint32_t a = sV + (uint32_t)(j * 16 + v_nr) * SROWB
                                 + (uint32_t)(nbp * 16 + v_nc) * 2;
                ldsm4t(vh, a);
                mma_f16(o[2*nbp],   ph[j], vh[0], vh[1]);
                mma_f16(o[2*nbp+1], ph[j], vh[2], vh[3]);
            }
        }
    }

    // ---- finalize: write O hi-only in [B,S,D] ----
    l0 += __shfl_xor_sync(0xffffffffu, l0, 1);
    l0 += __shfl_xor_sync(0xffffffffu, l0, 2);
    l1 += __shfl_xor_sync(0xffffffffu, l1, 1);
    l1 += __shfl_xor_sync(0xffffffffu, l1, 2);
    const float inv0 = 1.f / l0, inv1 = 1.f / l1;

    const int b = bh >> 4, h = bh & 15;
    const int r0g = q0 + (w << 4) + (lane >> 2);
    #pragma unroll
    for (int nb = 0; nb < 8; ++nb) {
        const int col = h * 64 + nb * 8 + ((lane & 3) << 1);
        {
            const size_t idx = (size_t)(b * SEQ + r0g) * D_MODEL + col;
            *(uint32_t*)&Oh[idx] = f16x2pk(o[nb][0] * inv0, o[nb][1] * inv0);
        }
        {
            const size_t idx = (size_t)(b * SEQ + r0g + 8) * D_MODEL + col;
            *(uint32_t*)&Oh[idx] = f16x2pk(o[nb][2] * inv1, o[nb][3] * inv1);
        }
    }
}

// ---------------------------------------------------------------------------
extern "C" void kernel_launch(void* const* d_in, const int* in_sizes, int n_in,
                              void* d_out, int out_size)
{
    (void)in_sizes; (void)n_in; (void)out_size;
    const float* x  = (const float*)d_in[0];
    const float* Wq = (const float*)d_in[1];
    const float* bq = (const float*)d_in[2];
    const float* Wk = (const float*)d_in[3];
    const float* bk = (const float*)d_in[4];
    const float* Wv = (const float*)d_in[5];
    const float* bv = (const float*)d_in[6];
    const float* Wo = (const float*)d_in[7];
    const float* bo = (const float*)d_in[8];
    float* out = (float*)d_out;

    __half *Qh, *Kh, *Vh, *xh, *xl, *Wth, *Oh;
    cudaGetSymbolAddress((void**)&Qh,  g_Qh);
    cudaGetSymbolAddress((void**)&Kh,  g_Kh);
    cudaGetSymbolAddress((void**)&Vh,  g_Vh);
    cudaGetSymbolAddress((void**)&xh,  g_xh);  cudaGetSymbolAddress((void**)&xl, g_xl);
    cudaGetSymbolAddress((void**)&Wth, g_Wth);
    cudaGetSymbolAddress((void**)&Oh,  g_Oh);

    cudaFuncSetAttribute(gemm_qkv,
                         cudaFuncAttributeMaxDynamicSharedMemorySize, GEMM_SMEM);
    cudaFuncSetAttribute(gemm_out,
                         cudaFuncAttributeMaxDynamicSharedMemorySize, GEMM_SMEM);
    cudaFuncSetAttribute(flash_mma,
                         cudaFuncAttributeMaxDynamicSharedMemorySize, ATT_SMEM);

    const size_t WSZ = (size_t)D_MODEL * D_MODEL;

    // fused prep: x split + 4 weight transposes, one launch
    prep<<<dim3(32, 32, 5), 256>>>(x, Wq, Wk, Wv, Wo, xh, xl, Wth);

    dim3 gq(D_MODEL / 128, M_TOTAL / 128, 3);   // fused Q/K/V
    gemm_qkv<<<gq, 256, GEMM_SMEM>>>(xh, xl, Wth, bq, bk, bv, Qh, Kh, Vh);

    dim3 ga(SEQ / 64, BATCH * N_HEADS);
    flash_mma<<<ga, 128, ATT_SMEM>>>(Qh, Kh, Vh, Oh);

    dim3 gg(D_MODEL / 128, M_TOTAL / 128);
    gemm_out<<<gg, 256, GEMM_SMEM>>>(Oh, Wth + 3 * WSZ, bo, out);
}

// round 14
// speedup vs baseline: 1.3221x; 1.3221x over previous
#include <cuda_runtime.h>
#include <cuda_bf16.h>
#include <cuda_fp16.h>
#include <cstdint>

#define D_MODEL  1024
#define N_HEADS  16
#define HEAD_DIM 64
#define BATCH    2
#define SEQ      2048
#define M_TOTAL  (BATCH * SEQ)   // 4096
#define QSCALE   0.18033688011112042f   // 0.125 * log2(e)

// ---------------------------------------------------------------------------
// Device-global scratch (allocation-free rule) — all fp16, hi-only everywhere
// ---------------------------------------------------------------------------
#define PHSZ (BATCH * N_HEADS * SEQ * HEAD_DIM)   // 4M elems
__device__ __align__(16) __half g_Qh[PHSZ];
__device__ __align__(16) __half g_Kh[PHSZ];
__device__ __align__(16) __half g_Vh[PHSZ];
__device__ __align__(16) __half g_xh[M_TOTAL * D_MODEL];
__device__ __align__(16) __half g_Wth[4 * D_MODEL * D_MODEL]; // W^T hi [N,K]
__device__ __align__(16) __half g_Oh[M_TOTAL * D_MODEL];

// ---------------------------------------------------------------------------
// helpers (compute_103-legal: ldmatrix / mma.sync / cp.async / ex2.approx)
// ---------------------------------------------------------------------------
__device__ __forceinline__ uint32_t smem_u32(const void* p) {
    uint32_t a;
    asm("{ .reg .u64 t; cvta.to.shared.u64 t, %1; cvt.u32.u64 %0, t; }"
        : "=r"(a) : "l"(p));
    return a;
}
__device__ __forceinline__ void ldsm4(uint32_t* r, uint32_t addr) {
    asm volatile("ldmatrix.sync.aligned.m8n8.x4.shared.b16 {%0,%1,%2,%3}, [%4];"
        : "=r"(r[0]), "=r"(r[1]), "=r"(r[2]), "=r"(r[3]) : "r"(addr));
}
__device__ __forceinline__ void ldsm4t(uint32_t* r, uint32_t addr) {
    asm volatile("ldmatrix.sync.aligned.m8n8.x4.trans.shared.b16 {%0,%1,%2,%3}, [%4];"
        : "=r"(r[0]), "=r"(r[1]), "=r"(r[2]), "=r"(r[3]) : "r"(addr));
}
__device__ __forceinline__ void mma_f16(float* c, const uint32_t* a,
                                        uint32_t b0, uint32_t b1) {
    asm volatile(
        "mma.sync.aligned.m16n8k16.row.col.f32.f16.f16.f32 "
        "{%0,%1,%2,%3}, {%4,%5,%6,%7}, {%8,%9}, {%0,%1,%2,%3};"
        : "+f"(c[0]), "+f"(c[1]), "+f"(c[2]), "+f"(c[3])
        : "r"(a[0]), "r"(a[1]), "r"(a[2]), "r"(a[3]), "r"(b0), "r"(b1));
}
__device__ __forceinline__ float exp2a(float x) {
    float r; asm("ex2.approx.f32 %0, %1;" : "=f"(r) : "f"(x)); return r;
}
__device__ __forceinline__ uint32_t f16x2pk(float lo, float hi) {
    uint32_t r;
    asm("cvt.rn.f16x2.f32 %0, %1, %2;" : "=r"(r) : "f"(hi), "f"(lo));
    return r;
}

#define CP16(saddr, gptr) \
    asm volatile("cp.async.cg.shared.global [%0], [%1], 16;" \
        :: "r"(saddr), "l"(gptr) : "memory")
#define CP_COMMIT() asm volatile("cp.async.commit_group;" ::: "memory")
#define CP_WAIT0()  asm volatile("cp.async.wait_group 0;" ::: "memory")
#define CP_WAIT1()  asm volatile("cp.async.wait_group 1;" ::: "memory")

// ---------------------------------------------------------------------------
// Fused prep: z=0 -> x fp32 -> fp16; z=1..4 -> W transpose (hi).
// ---------------------------------------------------------------------------
__global__ __launch_bounds__(256) void prep(
    const float* __restrict__ x,
    const float* __restrict__ Wq, const float* __restrict__ Wk,
    const float* __restrict__ Wv, const float* __restrict__ Wo,
    __half* __restrict__ xh, __half* __restrict__ Wth)
{
    __shared__ float t[32][33];
    const int z = blockIdx.z;
    const int tid = threadIdx.x;

    if (z == 0) {
        const int bid = blockIdx.y * 32 + blockIdx.x;     // 0..1023
        #pragma unroll
        for (int it = 0; it < 4; ++it) {
            const int i = it * (1024 * 256) + bid * 256 + tid;
            float4 v = ((const float4*)x)[i];
            uint32_t h0 = f16x2pk(v.x, v.y), h1 = f16x2pk(v.z, v.w);
            ((uint2*)xh)[i] = make_uint2(h0, h1);
        }
        return;
    }

    const float* W = (z == 1) ? Wq : (z == 2) ? Wk : (z == 3) ? Wv : Wo;
    const size_t WSZ = (size_t)D_MODEL * D_MODEL;
    __half* Th = Wth + (size_t)(z - 1) * WSZ;

    const int bx = blockIdx.x * 32;   // n block
    const int by = blockIdx.y * 32;   // k block
    const int xx = tid & 31, yy = tid >> 5;   // 32 x 8
    #pragma unroll
    for (int j = 0; j < 32; j += 8)
        t[yy + j][xx] = W[(by + yy + j) * D_MODEL + bx + xx];
    __syncthreads();
    #pragma unroll
    for (int j = 0; j < 32; j += 8) {
        float v = t[xx][yy + j];               // (k=by+xx, n=bx+yy+j)
        Th[(bx + yy + j) * D_MODEL + by + xx] = __float2half_rn(v);
    }
}

// ---------------------------------------------------------------------------
// GEMM mainloop: fp16 1-term via mma.sync, 128x128 tile, K-chunk 32,
// 2-stage cp.async pipeline (R12 structure, known-good), 2 CTAs/SM.
// C = Ah * Bh
// ---------------------------------------------------------------------------
#define GK     32
#define NKCH   (D_MODEL / GK)        // 32
#define ROW_B  80
#define TILE_B (128 * ROW_B)         // 10240
#define STG_B  (2 * TILE_B)          // 20480 per stage (Ah, Bh)
#define GEMM_SMEM (2 * STG_B)        // 40960 (x2 CTAs = 80KB)

__device__ __forceinline__ void gemm_core1(
    const __half* __restrict__ Ah, const __half* __restrict__ Bh,
    uint32_t sb, int m0, int n0, float acc[4][4][4])
{
    const int tid  = threadIdx.x;
    const int lane = tid & 31;
    const int wid  = tid >> 5;
    const int wm = (wid & 1) * 64;
    const int wn = (wid >> 1) * 32;

    const int lrow = tid >> 1;
    const int lhalf = tid & 1;
    const __half* pAh = Ah + (size_t)(m0 + lrow) * D_MODEL + lhalf * 16;
    const __half* pBh = Bh + (size_t)(n0 + lrow) * D_MODEL + lhalf * 16;
    const uint32_t w0 = (uint32_t)lrow * ROW_B + (uint32_t)lhalf * 32u;
    const uint32_t w1 = w0 + 16u;

    const uint32_t a_off = (uint32_t)(wm + (lane & 15)) * ROW_B
                         + (uint32_t)(lane >> 4) * 16u;
    const uint32_t b_off = (uint32_t)(wn + ((lane >> 4) << 3) + (lane & 7)) * ROW_B
                         + (uint32_t)((lane >> 3) & 1) * 16u;

    #pragma unroll
    for (int i = 0; i < 4; ++i)
        #pragma unroll
        for (int j = 0; j < 4; ++j)
            #pragma unroll
            for (int r = 0; r < 4; ++r) acc[i][j][r] = 0.f;

    // prologue: chunk 0 -> stage 0
    {
        const uint32_t s = sb;
        CP16(s + w0,          pAh);
        CP16(s + w1,          pAh + 8);
        CP16(s + TILE_B + w0, pBh);
        CP16(s + TILE_B + w1, pBh + 8);
        CP_COMMIT();
    }

    for (int i = 0; i < NKCH; ++i) {
        if (i + 1 < NKCH) {
            const uint32_t s = sb + (uint32_t)((i + 1) & 1) * STG_B;
            const int e = (i + 1) * GK;
            CP16(s + w0,          pAh + e);
            CP16(s + w1,          pAh + e + 8);
            CP16(s + TILE_B + w0, pBh + e);
            CP16(s + TILE_B + w1, pBh + e + 8);
            CP_COMMIT();
            CP_WAIT1();
        } else {
            CP_WAIT0();
        }
        __syncthreads();

        const uint32_t stg = sb + (uint32_t)(i & 1) * STG_B;
        #pragma unroll
        for (int ks = 0; ks < 2; ++ks) {
            uint32_t bh[2][4];
            #pragma unroll
            for (int ng = 0; ng < 2; ++ng)
                ldsm4(bh[ng], stg + TILE_B + b_off + ng * (16 * ROW_B) + ks * 32);
            #pragma unroll
            for (int mt = 0; mt < 4; ++mt) {
                uint32_t ah[4];
                ldsm4(ah, stg + a_off + mt * (16 * ROW_B) + ks * 32);
                #pragma unroll
                for (int n8 = 0; n8 < 4; ++n8) {
                    const int ng = n8 >> 1, hf = (n8 & 1) * 2;
                    mma_f16(acc[mt][n8], ah, bh[ng][hf], bh[ng][hf + 1]);
                }
            }
        }

        if (i + 1 < NKCH)
            __syncthreads();
    }
}

// QKV projections fused: grid (8, 32, 3); z: 0=Q, 1=K, 2=V. 1-term, hi out.
__global__ __launch_bounds__(256, 2)
void gemm_qkv(const __half* __restrict__ xh,
              const __half* __restrict__ Wth,
              const float* __restrict__ bq, const float* __restrict__ bk,
              const float* __restrict__ bv,
              __half* __restrict__ Qh, __half* __restrict__ Kh,
              __half* __restrict__ Vh)
{
    extern __shared__ char smem[];
    const uint32_t sb = smem_u32(smem);
    const int z = blockIdx.z;
    const size_t WSZ = (size_t)D_MODEL * D_MODEL;
    const __half* Bh = Wth + (size_t)z * WSZ;
    const float* bias = (z == 0) ? bq : (z == 1) ? bk : bv;
    const float scale = (z == 0) ? QSCALE : 1.0f;
    __half* Ch = (z == 0) ? Qh : (z == 1) ? Kh : Vh;

    const int m0 = blockIdx.y * 128;
    const int n0 = blockIdx.x * 128;

    float acc[4][4][4];
    gemm_core1(xh, Bh, sb, m0, n0, acc);

    const int lane = threadIdx.x & 31;
    const int wid  = threadIdx.x >> 5;
    const int wm = (wid & 1) * 64, wn = (wid >> 1) * 32;
    const int mrow = lane >> 2, ncol = (lane & 3) * 2;
    #pragma unroll
    for (int mt = 0; mt < 4; ++mt) {
        #pragma unroll
        for (int n8 = 0; n8 < 4; ++n8) {
            const int n = n0 + wn + n8 * 8 + ncol;
            const float bx = bias[n], by = bias[n + 1];
            #pragma unroll
            for (int h2 = 0; h2 < 2; ++h2) {
                const int m = m0 + wm + mt * 16 + mrow + h2 * 8;
                const float vx = (acc[mt][n8][h2 * 2 + 0] + bx) * scale;
                const float vy = (acc[mt][n8][h2 * 2 + 1] + by) * scale;
                const int b = m >> 11, s = m & (SEQ - 1);
                const int hh = n >> 6, hd = n & 63;
                const size_t idx =
                    ((size_t)(b * N_HEADS + hh) * SEQ + s) * HEAD_DIM + hd;
                *(uint32_t*)&Ch[idx] = f16x2pk(vx, vy);
            }
        }
    }
}

// Output projection: 1-term fp16, fp32 out row-major.
__global__ __launch_bounds__(256, 2)
void gemm_out(const __half* __restrict__ Ah,
              const __half* __restrict__ Bh,
              const float* __restrict__ bias, float* __restrict__ C)
{
    extern __shared__ char smem[];
    const uint32_t sb = smem_u32(smem);
    const int m0 = blockIdx.y * 128;
    const int n0 = blockIdx.x * 128;

    float acc[4][4][4];
    gemm_core1(Ah, Bh, sb, m0, n0, acc);

    const int lane = threadIdx.x & 31;
    const int wid  = threadIdx.x >> 5;
    const int wm = (wid & 1) * 64, wn = (wid >> 1) * 32;
    const int mrow = lane >> 2, ncol = (lane & 3) * 2;
    #pragma unroll
    for (int mt = 0; mt < 4; ++mt) {
        #pragma unroll
        for (int n8 = 0; n8 < 4; ++n8) {
            const int n = n0 + wn + n8 * 8 + ncol;
            const float bx = bias[n], by = bias[n + 1];
            #pragma unroll
            for (int h2 = 0; h2 < 2; ++h2) {
                const int m = m0 + wm + mt * 16 + mrow + h2 * 8;
                float2 v;
                v.x = acc[mt][n8][h2 * 2 + 0] + bx;
                v.y = acc[mt][n8][h2 * 2 + 1] + by;
                *(float2*)&C[(size_t)m * D_MODEL + n] = v;
            }
        }
    }
}

// ---------------------------------------------------------------------------
// Tensor-core causal flash attention, fp16 operands (R12 known-good).
// S = Qh·Kh.  O += Ph·Vh.  Output hi only.
// cp.async double-buffered K/V pipeline; skip-rescale.
// ---------------------------------------------------------------------------
#define SROWB 144
#define ATILE (64 * SROWB)               // 9216
#define ATT_SMEM (5 * ATILE)             // 46080

__device__ __forceinline__ void cp_tile2(uint32_t sbase, const __half* gK,
                                         const __half* gV, int tid)
{
    #pragma unroll
    for (int i = 0; i < 4; ++i) {
        const int c = tid + 128 * i;
        const uint32_t sa = (uint32_t)(c >> 3) * SROWB + (uint32_t)(c & 7) * 16u;
        CP16(sbase + sa, gK + 8 * c);
        CP16(sbase + ATILE + sa, gV + 8 * c);
    }
}

__global__ __launch_bounds__(128)
void flash_mma(const __half* __restrict__ Qh_,
               const __half* __restrict__ Kh_, const __half* __restrict__ Vh_,
               __half* __restrict__ Oh)
{
    extern __shared__ char smem[];
    const uint32_t sb = smem_u32(smem);

    const int tid = threadIdx.x, lane = tid & 31, w = tid >> 5;
    const int bh = blockIdx.y;
    const int qb = gridDim.x - 1 - blockIdx.x;   // long blocks first
    const int q0 = qb * 64;
    const size_t base = (size_t)bh * SEQ * HEAD_DIM;

    // prologue: Q + K/V stage 0, one cp.async group
    {
        const __half* gQh = Qh_ + base + (size_t)q0 * 64;
        #pragma unroll
        for (int i = 0; i < 4; ++i) {
            const int c = tid + 128 * i;
            const uint32_t sa = (uint32_t)(c >> 3) * SROWB + (uint32_t)(c & 7) * 16u;
            CP16(sb + sa, gQh + 8 * c);
        }
        cp_tile2(sb + ATILE, Kh_ + base, Vh_ + base, tid);
        CP_COMMIT();
    }

    const uint32_t k_nr = (uint32_t)((lane & 7) + ((lane >> 4) << 3));
    const uint32_t k_nc = (uint32_t)(((lane >> 3) & 1) << 3);
    const uint32_t v_nr = (uint32_t)((lane & 7) + (((lane >> 3) & 1) << 3));
    const uint32_t v_nc = (uint32_t)((lane >> 4) << 3);

    uint32_t qh[4][4];
    float o[8][4];
    #pragma unroll
    for (int i = 0; i < 8; ++i)
        #pragma unroll
        for (int j = 0; j < 4; ++j) o[i][j] = 0.f;
    float m0 = -1e30f, m1 = -1e30f, l0 = 0.f, l1 = 0.f;

    const int nt = q0 >> 6;
    for (int it = 0; it <= nt; ++it) {
        __syncthreads();              // all warps done reading stage it^1
        if (it < nt) {
            const size_t g = base + (size_t)(it + 1) * 64 * 64;
            cp_tile2(sb + ATILE + (uint32_t)((it + 1) & 1) * 2 * ATILE,
                     Kh_ + g, Vh_ + g, tid);
            CP_COMMIT();
            CP_WAIT1();
        } else {
            CP_WAIT0();
        }
        __syncthreads();

        if (it == 0) {                // Q fragments (once)
            const int r = (w << 4) + (lane & 15);
            const int c = (lane >> 4) << 3;
            #pragma unroll
            for (int kc = 0; kc < 4; ++kc)
                ldsm4(qh[kc], sb + (uint32_t)r * SROWB
                              + (uint32_t)(kc * 16 + c) * 2);
        }

        const uint32_t sK = sb + ATILE + (uint32_t)(it & 1) * 2 * ATILE;
        const uint32_t sV = sK + ATILE;

        // ---- S = Qh Kh^T ----
        float s[8][4];
        #pragma unroll
        for (int i = 0; i < 8; ++i)
            #pragma unroll
            for (int j = 0; j < 4; ++j) s[i][j] = 0.f;

        #pragma unroll
        for (int nbp = 0; nbp < 4; ++nbp) {
            #pragma unroll
            for (int kc = 0; kc < 4; ++kc) {
                uint32_t kh[4];
                const uint32_t a = sK + (uint32_t)(nbp * 16 + k_nr) * SROWB
                                 + (uint32_t)(kc * 16 + k_nc) * 2;
                ldsm4(kh, a);
                mma_f16(s[2*nbp],   qh[kc], kh[0], kh[1]);
                mma_f16(s[2*nbp+1], qh[kc], kh[2], kh[3]);
            }
        }

        // ---- causal mask (diagonal tile only) ----
        if (it == nt) {
            const int rb = (w << 4) + (lane >> 2);
            #pragma unroll
            for (int nb = 0; nb < 8; ++nb) {
                const int c = nb * 8 + ((lane & 3) << 1);
                if (c     > rb)     s[nb][0] = -1e30f;
                if (c + 1 > rb)     s[nb][1] = -1e30f;
                if (c     > rb + 8) s[nb][2] = -1e30f;
                if (c + 1 > rb + 8) s[nb][3] = -1e30f;
            }
        }

        // ---- online softmax (log2 domain), skip rescale if max unchanged ----
        float mt0 = -1e30f, mt1 = -1e30f;
        #pragma unroll
        for (int nb = 0; nb < 8; ++nb) {
            mt0 = fmaxf(mt0, fmaxf(s[nb][0], s[nb][1]));
            mt1 = fmaxf(mt1, fmaxf(s[nb][2], s[nb][3]));
        }
        mt0 = fmaxf(mt0, __shfl_xor_sync(0xffffffffu, mt0, 1));
        mt0 = fmaxf(mt0, __shfl_xor_sync(0xffffffffu, mt0, 2));
        mt1 = fmaxf(mt1, __shfl_xor_sync(0xffffffffu, mt1, 1));
        mt1 = fmaxf(mt1, __shfl_xor_sync(0xffffffffu, mt1, 2));
        if (mt0 > m0 || mt1 > m1) {
            const float mn0 = fmaxf(m0, mt0), mn1 = fmaxf(m1, mt1);
            const float c0 = exp2a(m0 - mn0), c1 = exp2a(m1 - mn1);
            m0 = mn0; m1 = mn1;
            l0 *= c0;  l1 *= c1;
            #pragma unroll
            for (int nb = 0; nb < 8; ++nb) {
                o[nb][0] *= c0; o[nb][1] *= c0; o[nb][2] *= c1; o[nb][3] *= c1;
            }
        }

        uint32_t ph[4][4];
        #pragma unroll
        for (int nb = 0; nb < 8; ++nb) {
            const float p0 = exp2a(s[nb][0] - m0);
            const float p1 = exp2a(s[nb][1] - m0);
            const float p2 = exp2a(s[nb][2] - m1);
            const float p3 = exp2a(s[nb][3] - m1);
            l0 += p0 + p1;  l1 += p2 + p3;
            const int j = nb >> 1, q = (nb & 1) << 1;
            ph[j][q]     = f16x2pk(p0, p1);
            ph[j][q + 1] = f16x2pk(p2, p3);
        }

        // ---- O += Ph Vh ----
        #pragma unroll
        for (int j = 0; j < 4; ++j) {
            #pragma unroll
            for (int nbp = 0; nbp < 4; ++nbp) {
                uint32_t vh[4];
                const uint32_t a = sV + (uint32_t)(j * 16 + v_nr) * SROWB
                                 + (uint32_t)(nbp * 16 + v_nc) * 2;
                ldsm4t(vh, a);
                mma_f16(o[2*nbp],   ph[j], vh[0], vh[1]);
                mma_f16(o[2*nbp+1], ph[j], vh[2], vh[3]);
            }
        }
    }

    // ---- finalize: write O hi-only in [B,S,D] ----
    l0 += __shfl_xor_sync(0xffffffffu, l0, 1);
    l0 += __shfl_xor_sync(0xffffffffu, l0, 2);
    l1 += __shfl_xor_sync(0xffffffffu, l1, 1);
    l1 += __shfl_xor_sync(0xffffffffu, l1, 2);
    const float inv0 = 1.f / l0, inv1 = 1.f / l1;

    const int b = bh >> 4, h = bh & 15;
    const int r0g = q0 + (w << 4) + (lane >> 2);
    #pragma unroll
    for (int nb = 0; nb < 8; ++nb) {
        const int col = h * 64 + nb * 8 + ((lane & 3) << 1);
        {
            const size_t idx = (size_t)(b * SEQ + r0g) * D_MODEL + col;
            *(uint32_t*)&Oh[idx] = f16x2pk(o[nb][0] * inv0, o[nb][1] * inv0);
        }
        {
            const size_t idx = (size_t)(b * SEQ + r0g + 8) * D_MODEL + col;
            *(uint32_t*)&Oh[idx] = f16x2pk(o[nb][2] * inv1, o[nb][3] * inv1);
        }
    }
}

// ---------------------------------------------------------------------------
extern "C" void kernel_launch(void* const* d_in, const int* in_sizes, int n_in,
                              void* d_out, int out_size)
{
    (void)in_sizes; (void)n_in; (void)out_size;
    const float* x  = (const float*)d_in[0];
    const float* Wq = (const float*)d_in[1];
    const float* bq = (const float*)d_in[2];
    const float* Wk = (const float*)d_in[3];
    const float* bk = (const float*)d_in[4];
    const float* Wv = (const float*)d_in[5];
    const float* bv = (const float*)d_in[6];
    const float* Wo = (const float*)d_in[7];
    const float* bo = (const float*)d_in[8];
    float* out = (float*)d_out;

    __half *Qh, *Kh, *Vh, *xh, *Wth, *Oh;
    cudaGetSymbolAddress((void**)&Qh,  g_Qh);
    cudaGetSymbolAddress((void**)&Kh,  g_Kh);
    cudaGetSymbolAddress((void**)&Vh,  g_Vh);
    cudaGetSymbolAddress((void**)&xh,  g_xh);
    cudaGetSymbolAddress((void**)&Wth, g_Wth);
    cudaGetSymbolAddress((void**)&Oh,  g_Oh);

    cudaFuncSetAttribute(gemm_qkv,
                         cudaFuncAttributeMaxDynamicSharedMemorySize, GEMM_SMEM);
    cudaFuncSetAttribute(gemm_out,
                         cudaFuncAttributeMaxDynamicSharedMemorySize, GEMM_SMEM);
    cudaFuncSetAttribute(flash_mma,
                         cudaFuncAttributeMaxDynamicSharedMemorySize, ATT_SMEM);

    const size_t WSZ = (size_t)D_MODEL * D_MODEL;

    // fused prep: x convert + 4 weight transposes, one launch
    prep<<<dim3(32, 32, 5), 256>>>(x, Wq, Wk, Wv, Wo, xh, Wth);

    dim3 gq(D_MODEL / 128, M_TOTAL / 128, 3);   // fused Q/K/V
    gemm_qkv<<<gq, 256, GEMM_SMEM>>>(xh, Wth, bq, bk, bv, Qh, Kh, Vh);

    dim3 ga(SEQ / 64, BATCH * N_HEADS);
    flash_mma<<<ga, 128, ATT_SMEM>>>(Qh, Kh, Vh, Oh);

    dim3 gg(D_MODEL / 128, M_TOTAL / 128);
    gemm_out<<<gg, 256, GEMM_SMEM>>>(Oh, Wth + 3 * WSZ, bo, out);
}